// round 11
// baseline (speedup 1.0000x reference)
#include <cuda_runtime.h>
#include <cuda_bf16.h>
#include <cstdint>

#define Pn    784
#define BATCH 16
#define CIN   512
#define CMID  128
#define CRED  32
#define NG    8
#define KK    49
#define CSPAN 392   // KK * NG

// Scratch (device globals: allocation-free rule)
__device__ float g_out1[BATCH * CMID * Pn];                 // 6.4 MB
__device__ float g_w[BATCH * CSPAN * Pn];                   // 19.7 MB
__device__ __nv_bfloat16 g_o2h[BATCH * CMID * Pn];          // 3.2 MB
__device__ __nv_bfloat16 g_o2l[BATCH * CMID * Pn];          // 3.2 MB
__device__ __nv_bfloat16 g_w3h[CIN * CMID];
__device__ __nv_bfloat16 g_w3l[CIN * CMID];

// ============================================================================
// helpers
// ============================================================================
__device__ __forceinline__ uint32_t smem_u32(const void* p) {
    uint32_t a;
    asm("{ .reg .u64 t; cvta.to.shared.u64 t, %1; cvt.u32.u64 %0, t; }"
        : "=r"(a) : "l"(p));
    return a;
}
__device__ __forceinline__ void mma_bf16(float* d, const uint32_t* a, const uint32_t* b) {
    asm volatile(
        "mma.sync.aligned.m16n8k16.row.col.f32.bf16.bf16.f32 "
        "{%0,%1,%2,%3}, {%4,%5,%6,%7}, {%8,%9}, {%0,%1,%2,%3};"
        : "+f"(d[0]), "+f"(d[1]), "+f"(d[2]), "+f"(d[3])
        : "r"(a[0]), "r"(a[1]), "r"(a[2]), "r"(a[3]), "r"(b[0]), "r"(b[1]));
}
__device__ __forceinline__ void ldsm_x4(uint32_t* r, uint32_t a) {
    asm volatile("ldmatrix.sync.aligned.m8n8.x4.shared.b16 {%0,%1,%2,%3}, [%4];"
        : "=r"(r[0]), "=r"(r[1]), "=r"(r[2]), "=r"(r[3]) : "r"(a));
}
__device__ __forceinline__ void ldsm_x4_t(uint32_t* r, uint32_t a) {
    asm volatile("ldmatrix.sync.aligned.m8n8.x4.trans.shared.b16 {%0,%1,%2,%3}, [%4];"
        : "=r"(r[0]), "=r"(r[1]), "=r"(r[2]), "=r"(r[3]) : "r"(a));
}
__device__ __forceinline__ void ldsm_x2_t(uint32_t* r, uint32_t a) {
    asm volatile("ldmatrix.sync.aligned.m8n8.x2.trans.shared.b16 {%0,%1}, [%2];"
        : "=r"(r[0]), "=r"(r[1]) : "r"(a));
}
__device__ __forceinline__ void cpa16(uint32_t dst, const void* src) {
    asm volatile("cp.async.ca.shared.global [%0], [%1], 16;" :: "r"(dst), "l"(src));
}
#define CP_COMMIT() asm volatile("cp.async.commit_group;" ::: "memory")
#define CP_WAIT0()  asm volatile("cp.async.wait_group 0;" ::: "memory")

__device__ __forceinline__ void split2(float f, __nv_bfloat16& h, __nv_bfloat16& l) {
    h = __float2bfloat16(f);
    l = __float2bfloat16(f - __bfloat162float(h));
}
__device__ __forceinline__ uint32_t pk2(__nv_bfloat16 a, __nv_bfloat16 b) {
    __nv_bfloat162 t = __halves2bfloat162(a, b);
    return *reinterpret_cast<uint32_t*>(&t);
}

// ============================================================================
// Shared GEMM tile geometry (conv1 / conv3). Split-bf16 3-term accumulation.
// ============================================================================
#define BM 128
#define BN 112
#define KC 64
#define SK 72
#define SN 120
#define A_E (BM * SK)
#define B_E (KC * SN)
#define STG_E (2 * A_E + 2 * B_E)
#define AEb (A_E * 2)
#define BEb (B_E * 2)

__device__ __forceinline__ void mma_chunk(float (&acc)[2][7][4],
                                          uint32_t aHiB, uint32_t bHiB,
                                          int lane, int warp_m, int warp_n) {
    const int l15 = lane & 15, l7 = lane & 7;
    const uint32_t aRow = (uint32_t)(warp_m + l15) * SK + ((lane >> 4) & 1) * 8;
#pragma unroll
    for (int ks = 0; ks < 4; ks++) {
        uint32_t ah[2][4], al[2][4];
#pragma unroll
        for (int i = 0; i < 2; i++) {
            uint32_t ad = aHiB + (aRow + (uint32_t)(i * 16 * SK + ks * 16)) * 2;
            ldsm_x4(ah[i], ad);
            ldsm_x4(al[i], ad + AEb);
        }
#pragma unroll
        for (int jp = 0; jp < 3; jp++) {
            uint32_t kr = (uint32_t)(ks * 16 + l7 + ((lane >> 3) & 1) * 8);
            uint32_t nc = (uint32_t)(warp_n + jp * 16 + (lane >> 4) * 8);
            uint32_t bd = bHiB + (kr * SN + nc) * 2;
            uint32_t rh[4], rl[4];
            ldsm_x4_t(rh, bd);
            ldsm_x4_t(rl, bd + BEb);
#pragma unroll
            for (int i = 0; i < 2; i++) {
                mma_bf16(acc[i][2*jp],   ah[i], rh + 0);
                mma_bf16(acc[i][2*jp],   ah[i], rl + 0);
                mma_bf16(acc[i][2*jp],   al[i], rh + 0);
                mma_bf16(acc[i][2*jp+1], ah[i], rh + 2);
                mma_bf16(acc[i][2*jp+1], ah[i], rl + 2);
                mma_bf16(acc[i][2*jp+1], al[i], rh + 2);
            }
        }
        {
            uint32_t kr = (uint32_t)(ks * 16 + l15);
            uint32_t bd = bHiB + (kr * SN + (uint32_t)(warp_n + 48)) * 2;
            uint32_t rh[2], rl[2];
            ldsm_x2_t(rh, bd);
            ldsm_x2_t(rl, bd + BEb);
#pragma unroll
            for (int i = 0; i < 2; i++) {
                mma_bf16(acc[i][6], ah[i], rh);
                mma_bf16(acc[i][6], ah[i], rl);
                mma_bf16(acc[i][6], al[i], rh);
            }
        }
    }
}

// ============================================================================
// conv1: 512->128, BN+ReLU. fp32 in-kernel split, double-buffered, reg-staged.
// ============================================================================
#define CONV1_SMEM (2 * STG_E * 2)

__global__ __launch_bounds__(256) void k_conv1mm(const float* __restrict__ W,
                                                 const float* __restrict__ scale,
                                                 const float* __restrict__ bias,
                                                 const float* __restrict__ x) {
    extern __shared__ __align__(16) __nv_bfloat16 smb[];
    const int tid = threadIdx.x, wid = tid >> 5, lane = tid & 31;
    const int b = blockIdx.y, n0 = blockIdx.x * BN;
    const int warp_m = (wid >> 1) * 32, warp_n = (wid & 1) * 56;
    const float* sb = x + (size_t)b * CIN * Pn;
    const uint32_t sbase = smem_u32(smb);

    float acc[2][7][4];
#pragma unroll
    for (int i = 0; i < 2; i++)
#pragma unroll
        for (int j = 0; j < 7; j++)
#pragma unroll
            for (int q = 0; q < 4; q++) acc[i][j][q] = 0.f;

    const int NT = CIN / KC;
    float4 sa[8], sv[7];

#pragma unroll
    for (int i = 0; i < 8; i++) {
        int u = tid + 256 * i; int m = u >> 4; int k4 = (u & 15) * 4;
        sa[i] = *(const float4*)&W[(size_t)m * CIN + k4];
    }
#pragma unroll
    for (int i = 0; i < 7; i++) {
        int u = tid + 256 * i; int k = u / 28; int n4 = (u - k * 28) * 4;
        sv[i] = *(const float4*)&sb[(size_t)k * Pn + n0 + n4];
    }

#pragma unroll 1
    for (int t = 0; t < NT; t++) {
        const int buf = t & 1;
        {
            __nv_bfloat16* aHi = smb + buf * STG_E;
            __nv_bfloat16* aLo = aHi + A_E;
            __nv_bfloat16* bHi = aLo + A_E;
            __nv_bfloat16* bLo = bHi + B_E;
#pragma unroll
            for (int i = 0; i < 8; i++) {
                int u = tid + 256 * i; int m = u >> 4; int k4 = (u & 15) * 4;
                __nv_bfloat16 h0,h1,h2,h3,l0,l1,l2,l3;
                split2(sa[i].x, h0, l0); split2(sa[i].y, h1, l1);
                split2(sa[i].z, h2, l2); split2(sa[i].w, h3, l3);
                *(uint2*)&aHi[m * SK + k4] = make_uint2(pk2(h0,h1), pk2(h2,h3));
                *(uint2*)&aLo[m * SK + k4] = make_uint2(pk2(l0,l1), pk2(l2,l3));
            }
#pragma unroll
            for (int i = 0; i < 7; i++) {
                int u = tid + 256 * i; int k = u / 28; int n4 = (u - k * 28) * 4;
                __nv_bfloat16 h0,h1,h2,h3,l0,l1,l2,l3;
                split2(sv[i].x, h0, l0); split2(sv[i].y, h1, l1);
                split2(sv[i].z, h2, l2); split2(sv[i].w, h3, l3);
                *(uint2*)&bHi[k * SN + n4] = make_uint2(pk2(h0,h1), pk2(h2,h3));
                *(uint2*)&bLo[k * SN + n4] = make_uint2(pk2(l0,l1), pk2(l2,l3));
            }
        }
        if (t + 1 < NT) {
#pragma unroll
            for (int i = 0; i < 8; i++) {
                int u = tid + 256 * i; int m = u >> 4; int k4 = (u & 15) * 4;
                sa[i] = *(const float4*)&W[(size_t)m * CIN + (t + 1) * KC + k4];
            }
#pragma unroll
            for (int i = 0; i < 7; i++) {
                int u = tid + 256 * i; int k = u / 28; int n4 = (u - k * 28) * 4;
                sv[i] = *(const float4*)&sb[(size_t)((t + 1) * KC + k) * Pn + n0 + n4];
            }
        }
        __syncthreads();
        uint32_t aHiB = sbase + buf * STG_E * 2;
        mma_chunk(acc, aHiB, aHiB + 2 * AEb, lane, warp_m, warp_n);
    }

    const int r0 = lane >> 2, c0 = (lane & 3) * 2;
#pragma unroll
    for (int i = 0; i < 2; i++) {
        const int mA = warp_m + i * 16 + r0;
        const int mB = mA + 8;
        const float scA = scale[mA], biA = bias[mA];
        const float scB = scale[mB], biB = bias[mB];
        float* dA = g_out1 + ((size_t)b * CMID + mA) * Pn;
        float* dB = g_out1 + ((size_t)b * CMID + mB) * Pn;
#pragma unroll
        for (int j = 0; j < 7; j++) {
            const int n = n0 + warp_n + j * 8 + c0;
            float2 vA = {fmaxf(acc[i][j][0] * scA + biA, 0.f),
                         fmaxf(acc[i][j][1] * scA + biA, 0.f)};
            float2 vB = {fmaxf(acc[i][j][2] * scB + biB, 0.f),
                         fmaxf(acc[i][j][3] * scB + biB, 0.f)};
            *(float2*)&dA[n] = vA;
            *(float2*)&dB[n] = vB;
        }
    }
}

// ============================================================================
// conv3: 128->512, BN + residual. Pre-split operands, pure cp.async, 2 CTAs/SM.
// ============================================================================
#define CONV3_SMEM (STG_E * 2)

__global__ __launch_bounds__(256, 2) void k_conv3mm(const float* __restrict__ scale,
                                                    const float* __restrict__ bias,
                                                    const float* __restrict__ x,
                                                    float* __restrict__ out) {
    extern __shared__ __align__(16) __nv_bfloat16 smb[];
    const int tid = threadIdx.x, wid = tid >> 5, lane = tid & 31;
    const int b = blockIdx.y, n0 = blockIdx.x * BN, mo = blockIdx.z * BM;
    const int warp_m = (wid >> 1) * 32, warp_n = (wid & 1) * 56;
    const uint32_t aHiB = smem_u32(smb);
    const uint32_t bHiB = aHiB + 2 * AEb;

    float acc[2][7][4];
#pragma unroll
    for (int i = 0; i < 2; i++)
#pragma unroll
        for (int j = 0; j < 7; j++)
#pragma unroll
            for (int q = 0; q < 4; q++) acc[i][j][q] = 0.f;

#pragma unroll 1
    for (int t = 0; t < 2; t++) {
        if (t) __syncthreads();
#pragma unroll
        for (int i = 0; i < 8; i++) {
            int q = tid + 256 * i;
            int plane = q >> 10, m = (q >> 3) & 127, j = q & 7;
            uint32_t dst = aHiB + (uint32_t)plane * AEb + (uint32_t)(m * SK + j * 8) * 2;
            const __nv_bfloat16* wp = plane ? g_w3l : g_w3h;
            cpa16(dst, wp + (size_t)(mo + m) * CMID + t * KC + j * 8);
        }
#pragma unroll
        for (int i = 0; i < 7; i++) {
            int q = tid + 256 * i;
            int plane = q >= 896;
            int r = plane ? q - 896 : q;
            int k = r / 14, j = r - k * 14;
            uint32_t dst = bHiB + (uint32_t)plane * BEb + (uint32_t)(k * SN + j * 8) * 2;
            const __nv_bfloat16* op = plane ? g_o2l : g_o2h;
            cpa16(dst, op + ((size_t)b * CMID + t * KC + k) * Pn + n0 + j * 8);
        }
        CP_COMMIT();
        CP_WAIT0();
        __syncthreads();
        mma_chunk(acc, aHiB, bHiB, lane, warp_m, warp_n);
    }

    const int r0 = lane >> 2, c0 = (lane & 3) * 2;
#pragma unroll
    for (int i = 0; i < 2; i++) {
        const int mA = mo + warp_m + i * 16 + r0;
        const int mB = mA + 8;
        const float scA = scale[mA], biA = bias[mA];
        const float scB = scale[mB], biB = bias[mB];
        float* dA = out + ((size_t)b * CIN + mA) * Pn;
        float* dB = out + ((size_t)b * CIN + mB) * Pn;
        const float* rA = x + ((size_t)b * CIN + mA) * Pn;
        const float* rB = x + ((size_t)b * CIN + mB) * Pn;
#pragma unroll
        for (int j = 0; j < 7; j++) {
            const int n = n0 + warp_n + j * 8 + c0;
            float2 qA = *(const float2*)&rA[n];
            float2 qB = *(const float2*)&rB[n];
            float2 vA = {acc[i][j][0] * scA + biA + qA.x,
                         acc[i][j][1] * scA + biA + qA.y};
            float2 vB = {acc[i][j][2] * scB + biB + qB.x,
                         acc[i][j][3] * scB + biB + qB.y};
            *(float2*)&dA[n] = vA;
            *(float2*)&dB[n] = vB;
        }
    }
}

// ---------------------------------------------------------------------------
// W3 pre-split: f32 -> bf16 hi/lo
// ---------------------------------------------------------------------------
__global__ void k_splitw(const float* __restrict__ src) {
    int i = blockIdx.x * 256 + threadIdx.x;
    if (i < CIN * CMID) {
        __nv_bfloat16 h, l;
        split2(src[i], h, l);
        g_w3h[i] = h;
        g_w3l[i] = l;
    }
}

// ---------------------------------------------------------------------------
// Kernel 2: involution kernel generation — register-tiled (R8 version)
// ---------------------------------------------------------------------------
#define WRT_S 36
#define KGEN_SMEM ((16384 + 128 * WRT_S + 4096 + 12544) * 4)

__global__ __launch_bounds__(256) void k_kgen(const float* __restrict__ Wr,
                                              const float* __restrict__ sr,
                                              const float* __restrict__ br,
                                              const float* __restrict__ Ws,
                                              const float* __restrict__ bs) {
    extern __shared__ float smk[];
    float* t1   = smk;
    float* WrT  = t1 + 16384;
    float* rshT = WrT + 128 * WRT_S;
    float* WsT  = rshT + 4096;

    const int b = blockIdx.y, n0 = blockIdx.x * 128, tid = threadIdx.x;
    const float* o1 = g_out1 + b * CMID * Pn;

#pragma unroll
    for (int i = 0; i < 16; i++) {
        int j = tid + 256 * i;
        int c = j >> 5, n4 = (j & 31) * 4;
        int n = n0 + n4;
        *(float4*)&t1[c * 128 + n4] =
            (n < Pn) ? *(const float4*)&o1[c * Pn + n] : make_float4(0.f,0.f,0.f,0.f);
    }
#pragma unroll
    for (int i = 0; i < 16; i++) {
        int j = tid + 256 * i;
        int m = j >> 7, c = j & 127;
        WrT[c * WRT_S + m] = Wr[j];
    }
#pragma unroll
    for (int i = 0; i < 49; i++) {
        int j = tid + 256 * i;
        int m = j >> 5, k = j & 31;
        WsT[k * 392 + m] = Ws[j];
    }
    __syncthreads();

    {
        const int mt = tid >> 5;
        const int nn = (tid & 31) * 4;
        float racc[4][4];
#pragma unroll
        for (int i = 0; i < 4; i++)
#pragma unroll
            for (int j = 0; j < 4; j++) racc[i][j] = 0.f;
#pragma unroll 8
        for (int c = 0; c < 128; c++) {
            float4 av = *(const float4*)&WrT[c * WRT_S + mt * 4];
            float4 bv = *(const float4*)&t1[c * 128 + nn];
            float ar[4] = {av.x, av.y, av.z, av.w};
            float bc[4] = {bv.x, bv.y, bv.z, bv.w};
#pragma unroll
            for (int i = 0; i < 4; i++)
#pragma unroll
                for (int j = 0; j < 4; j++) racc[i][j] += ar[i] * bc[j];
        }
#pragma unroll
        for (int i = 0; i < 4; i++) {
            int m = mt * 4 + i;
            float s = sr[m], bb = br[m];
            float4 v;
            v.x = fmaxf(racc[i][0]*s+bb, 0.f);
            v.y = fmaxf(racc[i][1]*s+bb, 0.f);
            v.z = fmaxf(racc[i][2]*s+bb, 0.f);
            v.w = fmaxf(racc[i][3]*s+bb, 0.f);
            *(float4*)&rshT[m * 128 + nn] = v;
        }
    }
    __syncthreads();

#pragma unroll 1
    for (int it = 0; it < 4; it++) {
        int unit = tid + 256 * it;
        if (unit >= 784) break;
        int mt = unit >> 4, nn = (unit & 15) * 8;
        float acc[8][8];
#pragma unroll
        for (int i = 0; i < 8; i++) {
            float bv = bs[mt * 8 + i];
#pragma unroll
            for (int j = 0; j < 8; j++) acc[i][j] = bv;
        }
#pragma unroll 8
        for (int k = 0; k < 32; k++) {
            float4 a0 = *(const float4*)&WsT[k * 392 + mt * 8];
            float4 a1 = *(const float4*)&WsT[k * 392 + mt * 8 + 4];
            float4 b0 = *(const float4*)&rshT[k * 128 + nn];
            float4 b1 = *(const float4*)&rshT[k * 128 + nn + 4];
            float ar[8] = {a0.x,a0.y,a0.z,a0.w,a1.x,a1.y,a1.z,a1.w};
            float bc[8] = {b0.x,b0.y,b0.z,b0.w,b1.x,b1.y,b1.z,b1.w};
#pragma unroll
            for (int i = 0; i < 8; i++)
#pragma unroll
                for (int j = 0; j < 8; j++) acc[i][j] += ar[i] * bc[j];
        }
        if (n0 + nn < Pn) {
#pragma unroll
            for (int i = 0; i < 8; i++) {
                int m = mt * 8 + i;
                float* wrow = g_w + (b * CSPAN + m) * Pn + n0 + nn;
                float4 v0 = {acc[i][0], acc[i][1], acc[i][2], acc[i][3]};
                float4 v1 = {acc[i][4], acc[i][5], acc[i][6], acc[i][7]};
                *(float4*)&wrow[0] = v0;
                *(float4*)&wrow[4] = v1;
            }
        }
    }
}

// ---------------------------------------------------------------------------
// Kernel 3: involution apply — vertical pixel pairing, channel-half BLOCKS.
// grid (2 y-halves, 16 group-halves, 16 batch) = 512 blocks, 256 threads.
// Block owns 8 channels; tile 20x34x8ch, slot stride 12 words (conflict-free,
// banks 12*xc mod 32 tile all 32 banks in disjoint 4-word groups). 32.6 KB
// smem -> 3 CTAs/SM. Thread = pixel-pair (196 live).
// ---------------------------------------------------------------------------
#define APL_SLOT 12
#define APL_SMEM (20 * 34 * APL_SLOT * 4)   // 32,640 B

__global__ __launch_bounds__(256) void k_apply() {
    extern __shared__ __align__(16) float xs[];
    const int y0 = blockIdx.x * 14;
    const int gh = blockIdx.y;              // group-half: group = gh>>1, ch-half = gh&1
    const int g  = gh >> 1;
    const int h  = gh & 1;
    const int b  = blockIdx.z;
    const int tid = threadIdx.x;

    const float* o1 = g_out1 + (b * CMID + g * 16 + h * 8) * Pn;
    for (int j = tid; j < 20 * 34 * 8; j += 256) {
        int c    = j & 7;
        int slot = j >> 3;
        int xx = slot % 34, yy = slot / 34;
        int gy = y0 + yy - 3, gx = xx - 3;
        float v = 0.f;
        if (gy >= 0 && gy < 28 && gx >= 0 && gx < 28)
            v = o1[c * Pn + gy * 28 + gx];
        xs[slot * APL_SLOT + c] = v;
    }
    __syncthreads();

    if (tid < 196) {
        const int yA = (tid / 28) * 2;
        const int xc = tid % 28;
        const int hwA = (y0 + yA) * 28 + xc;
        const int hwB = hwA + 28;
        const float* wbase = g_w + ((size_t)b * CSPAN + (size_t)g * KK) * Pn;

        float accA[8], accB[8];
#pragma unroll
        for (int c = 0; c < 8; c++) { accA[c] = 0.f; accB[c] = 0.f; }

#pragma unroll
        for (int dx = 0; dx < 7; dx++) {
            float wA[7], wB[7];
#pragma unroll
            for (int dy = 0; dy < 7; dy++) {
                const size_t wo = (size_t)(dy * 7 + dx) * Pn;
                wA[dy] = wbase[wo + hwA];
                wB[dy] = wbase[wo + hwB];
            }
#pragma unroll
            for (int i = 0; i < 8; i++) {
                const float* base = &xs[((yA + i) * 34 + xc + dx) * APL_SLOT];
                float4 v0 = *(const float4*)&base[0];
                float4 v1 = *(const float4*)&base[4];
                if (i < 7) {
                    const float w = wA[i];
                    accA[0] += w*v0.x; accA[1] += w*v0.y; accA[2] += w*v0.z; accA[3] += w*v0.w;
                    accA[4] += w*v1.x; accA[5] += w*v1.y; accA[6] += w*v1.z; accA[7] += w*v1.w;
                }
                if (i >= 1) {
                    const float w = wB[i - 1];
                    accB[0] += w*v0.x; accB[1] += w*v0.y; accB[2] += w*v0.z; accB[3] += w*v0.w;
                    accB[4] += w*v1.x; accB[5] += w*v1.y; accB[6] += w*v1.z; accB[7] += w*v1.w;
                }
            }
        }

        const size_t baseA = (size_t)(b * CMID + g * 16 + h * 8) * Pn + hwA;
#pragma unroll
        for (int c = 0; c < 8; c++) {
            __nv_bfloat16 hh, ll;
            split2(accA[c], hh, ll);
            g_o2h[baseA + (size_t)c * Pn] = hh;
            g_o2l[baseA + (size_t)c * Pn] = ll;
        }
#pragma unroll
        for (int c = 0; c < 8; c++) {
            __nv_bfloat16 hh, ll;
            split2(accB[c], hh, ll);
            g_o2h[baseA + 28 + (size_t)c * Pn] = hh;
            g_o2l[baseA + 28 + (size_t)c * Pn] = ll;
        }
    }
}

// ---------------------------------------------------------------------------
extern "C" void kernel_launch(void* const* d_in, const int* in_sizes, int n_in,
                              void* d_out, int out_size) {
    const float* x  = (const float*)d_in[0];
    const float* W1 = (const float*)d_in[1];
    const float* s1 = (const float*)d_in[2];
    const float* b1 = (const float*)d_in[3];
    const float* Wr = (const float*)d_in[4];
    const float* sr = (const float*)d_in[5];
    const float* br = (const float*)d_in[6];
    const float* Ws = (const float*)d_in[7];
    const float* bs = (const float*)d_in[8];
    const float* W3 = (const float*)d_in[9];
    const float* s3 = (const float*)d_in[10];
    const float* b3 = (const float*)d_in[11];
    float* out = (float*)d_out;

    cudaFuncSetAttribute(k_kgen, cudaFuncAttributeMaxDynamicSharedMemorySize, KGEN_SMEM);
    cudaFuncSetAttribute(k_apply, cudaFuncAttributeMaxDynamicSharedMemorySize, APL_SMEM);
    cudaFuncSetAttribute(k_conv1mm, cudaFuncAttributeMaxDynamicSharedMemorySize, CONV1_SMEM);
    cudaFuncSetAttribute(k_conv3mm, cudaFuncAttributeMaxDynamicSharedMemorySize, CONV3_SMEM);

    // W3 pre-split (independent of everything else)
    k_splitw<<<(CIN * CMID + 255) / 256, 256>>>(W3);
    // conv1: 512 -> 128, BN+ReLU
    k_conv1mm<<<dim3(7, 16), 256, CONV1_SMEM>>>(W1, s1, b1, x);
    // involution kernel generation
    k_kgen<<<dim3(7, 16), 256, KGEN_SMEM>>>(Wr, sr, br, Ws, bs);
    // involution apply (channel-half blocks, emits split-bf16 o2)
    k_apply<<<dim3(2, 2 * NG, BATCH), 256, APL_SMEM>>>();
    // conv3: 128 -> 512, BN + residual
    k_conv3mm<<<dim3(7, 16, 4), 256, CONV3_SMEM>>>(s3, b3, x, out);
}

// round 12
// speedup vs baseline: 1.0724x; 1.0724x over previous
#include <cuda_runtime.h>
#include <cuda_bf16.h>
#include <cstdint>

#define Pn    784
#define BATCH 16
#define CIN   512
#define CMID  128
#define CRED  32
#define NG    8
#define KK    49
#define CSPAN 392   // KK * NG

// Scratch (device globals: allocation-free rule)
__device__ float g_out1[BATCH * CMID * Pn];                 // 6.4 MB
__device__ float g_w[BATCH * CSPAN * Pn];                   // 19.7 MB
__device__ __nv_bfloat16 g_o2h[BATCH * CMID * Pn];          // 3.2 MB
__device__ __nv_bfloat16 g_o2l[BATCH * CMID * Pn];          // 3.2 MB
__device__ __nv_bfloat16 g_w3h[CIN * CMID];
__device__ __nv_bfloat16 g_w3l[CIN * CMID];
__device__ __nv_bfloat16 g_wsh[400 * CRED];                 // Ws split, 400-row pad
__device__ __nv_bfloat16 g_wsl[400 * CRED];

// ============================================================================
// helpers
// ============================================================================
__device__ __forceinline__ uint32_t smem_u32(const void* p) {
    uint32_t a;
    asm("{ .reg .u64 t; cvta.to.shared.u64 t, %1; cvt.u32.u64 %0, t; }"
        : "=r"(a) : "l"(p));
    return a;
}
__device__ __forceinline__ void mma_bf16(float* d, const uint32_t* a, const uint32_t* b) {
    asm volatile(
        "mma.sync.aligned.m16n8k16.row.col.f32.bf16.bf16.f32 "
        "{%0,%1,%2,%3}, {%4,%5,%6,%7}, {%8,%9}, {%0,%1,%2,%3};"
        : "+f"(d[0]), "+f"(d[1]), "+f"(d[2]), "+f"(d[3])
        : "r"(a[0]), "r"(a[1]), "r"(a[2]), "r"(a[3]), "r"(b[0]), "r"(b[1]));
}
__device__ __forceinline__ void ldsm_x4(uint32_t* r, uint32_t a) {
    asm volatile("ldmatrix.sync.aligned.m8n8.x4.shared.b16 {%0,%1,%2,%3}, [%4];"
        : "=r"(r[0]), "=r"(r[1]), "=r"(r[2]), "=r"(r[3]) : "r"(a));
}
__device__ __forceinline__ void ldsm_x4_t(uint32_t* r, uint32_t a) {
    asm volatile("ldmatrix.sync.aligned.m8n8.x4.trans.shared.b16 {%0,%1,%2,%3}, [%4];"
        : "=r"(r[0]), "=r"(r[1]), "=r"(r[2]), "=r"(r[3]) : "r"(a));
}
__device__ __forceinline__ void ldsm_x2_t(uint32_t* r, uint32_t a) {
    asm volatile("ldmatrix.sync.aligned.m8n8.x2.trans.shared.b16 {%0,%1}, [%2];"
        : "=r"(r[0]), "=r"(r[1]) : "r"(a));
}
__device__ __forceinline__ void cpa16(uint32_t dst, const void* src) {
    asm volatile("cp.async.ca.shared.global [%0], [%1], 16;" :: "r"(dst), "l"(src));
}
#define CP_COMMIT() asm volatile("cp.async.commit_group;" ::: "memory")
#define CP_WAIT0()  asm volatile("cp.async.wait_group 0;" ::: "memory")

__device__ __forceinline__ void split2(float f, __nv_bfloat16& h, __nv_bfloat16& l) {
    h = __float2bfloat16(f);
    l = __float2bfloat16(f - __bfloat162float(h));
}
__device__ __forceinline__ uint32_t pk2(__nv_bfloat16 a, __nv_bfloat16 b) {
    __nv_bfloat162 t = __halves2bfloat162(a, b);
    return *reinterpret_cast<uint32_t*>(&t);
}

// ============================================================================
// Shared GEMM tile geometry (conv1 / conv3). Split-bf16 3-term accumulation.
// ============================================================================
#define BM 128
#define BN 112
#define KC 64
#define SK 72
#define SN 120
#define A_E (BM * SK)
#define B_E (KC * SN)
#define STG_E (2 * A_E + 2 * B_E)
#define AEb (A_E * 2)
#define BEb (B_E * 2)

__device__ __forceinline__ void mma_chunk(float (&acc)[2][7][4],
                                          uint32_t aHiB, uint32_t bHiB,
                                          int lane, int warp_m, int warp_n) {
    const int l15 = lane & 15, l7 = lane & 7;
    const uint32_t aRow = (uint32_t)(warp_m + l15) * SK + ((lane >> 4) & 1) * 8;
#pragma unroll
    for (int ks = 0; ks < 4; ks++) {
        uint32_t ah[2][4], al[2][4];
#pragma unroll
        for (int i = 0; i < 2; i++) {
            uint32_t ad = aHiB + (aRow + (uint32_t)(i * 16 * SK + ks * 16)) * 2;
            ldsm_x4(ah[i], ad);
            ldsm_x4(al[i], ad + AEb);
        }
#pragma unroll
        for (int jp = 0; jp < 3; jp++) {
            uint32_t kr = (uint32_t)(ks * 16 + l7 + ((lane >> 3) & 1) * 8);
            uint32_t nc = (uint32_t)(warp_n + jp * 16 + (lane >> 4) * 8);
            uint32_t bd = bHiB + (kr * SN + nc) * 2;
            uint32_t rh[4], rl[4];
            ldsm_x4_t(rh, bd);
            ldsm_x4_t(rl, bd + BEb);
#pragma unroll
            for (int i = 0; i < 2; i++) {
                mma_bf16(acc[i][2*jp],   ah[i], rh + 0);
                mma_bf16(acc[i][2*jp],   ah[i], rl + 0);
                mma_bf16(acc[i][2*jp],   al[i], rh + 0);
                mma_bf16(acc[i][2*jp+1], ah[i], rh + 2);
                mma_bf16(acc[i][2*jp+1], ah[i], rl + 2);
                mma_bf16(acc[i][2*jp+1], al[i], rh + 2);
            }
        }
        {
            uint32_t kr = (uint32_t)(ks * 16 + l15);
            uint32_t bd = bHiB + (kr * SN + (uint32_t)(warp_n + 48)) * 2;
            uint32_t rh[2], rl[2];
            ldsm_x2_t(rh, bd);
            ldsm_x2_t(rl, bd + BEb);
#pragma unroll
            for (int i = 0; i < 2; i++) {
                mma_bf16(acc[i][6], ah[i], rh);
                mma_bf16(acc[i][6], ah[i], rl);
                mma_bf16(acc[i][6], al[i], rh);
            }
        }
    }
}

// ============================================================================
// conv1: 512->128, BN+ReLU. fp32 in-kernel split, double-buffered, reg-staged.
// ============================================================================
#define CONV1_SMEM (2 * STG_E * 2)

__global__ __launch_bounds__(256) void k_conv1mm(const float* __restrict__ W,
                                                 const float* __restrict__ scale,
                                                 const float* __restrict__ bias,
                                                 const float* __restrict__ x) {
    extern __shared__ __align__(16) __nv_bfloat16 smb[];
    const int tid = threadIdx.x, wid = tid >> 5, lane = tid & 31;
    const int b = blockIdx.y, n0 = blockIdx.x * BN;
    const int warp_m = (wid >> 1) * 32, warp_n = (wid & 1) * 56;
    const float* sb = x + (size_t)b * CIN * Pn;
    const uint32_t sbase = smem_u32(smb);

    float acc[2][7][4];
#pragma unroll
    for (int i = 0; i < 2; i++)
#pragma unroll
        for (int j = 0; j < 7; j++)
#pragma unroll
            for (int q = 0; q < 4; q++) acc[i][j][q] = 0.f;

    const int NT = CIN / KC;
    float4 sa[8], sv[7];

#pragma unroll
    for (int i = 0; i < 8; i++) {
        int u = tid + 256 * i; int m = u >> 4; int k4 = (u & 15) * 4;
        sa[i] = *(const float4*)&W[(size_t)m * CIN + k4];
    }
#pragma unroll
    for (int i = 0; i < 7; i++) {
        int u = tid + 256 * i; int k = u / 28; int n4 = (u - k * 28) * 4;
        sv[i] = *(const float4*)&sb[(size_t)k * Pn + n0 + n4];
    }

#pragma unroll 1
    for (int t = 0; t < NT; t++) {
        const int buf = t & 1;
        {
            __nv_bfloat16* aHi = smb + buf * STG_E;
            __nv_bfloat16* aLo = aHi + A_E;
            __nv_bfloat16* bHi = aLo + A_E;
            __nv_bfloat16* bLo = bHi + B_E;
#pragma unroll
            for (int i = 0; i < 8; i++) {
                int u = tid + 256 * i; int m = u >> 4; int k4 = (u & 15) * 4;
                __nv_bfloat16 h0,h1,h2,h3,l0,l1,l2,l3;
                split2(sa[i].x, h0, l0); split2(sa[i].y, h1, l1);
                split2(sa[i].z, h2, l2); split2(sa[i].w, h3, l3);
                *(uint2*)&aHi[m * SK + k4] = make_uint2(pk2(h0,h1), pk2(h2,h3));
                *(uint2*)&aLo[m * SK + k4] = make_uint2(pk2(l0,l1), pk2(l2,l3));
            }
#pragma unroll
            for (int i = 0; i < 7; i++) {
                int u = tid + 256 * i; int k = u / 28; int n4 = (u - k * 28) * 4;
                __nv_bfloat16 h0,h1,h2,h3,l0,l1,l2,l3;
                split2(sv[i].x, h0, l0); split2(sv[i].y, h1, l1);
                split2(sv[i].z, h2, l2); split2(sv[i].w, h3, l3);
                *(uint2*)&bHi[k * SN + n4] = make_uint2(pk2(h0,h1), pk2(h2,h3));
                *(uint2*)&bLo[k * SN + n4] = make_uint2(pk2(l0,l1), pk2(l2,l3));
            }
        }
        if (t + 1 < NT) {
#pragma unroll
            for (int i = 0; i < 8; i++) {
                int u = tid + 256 * i; int m = u >> 4; int k4 = (u & 15) * 4;
                sa[i] = *(const float4*)&W[(size_t)m * CIN + (t + 1) * KC + k4];
            }
#pragma unroll
            for (int i = 0; i < 7; i++) {
                int u = tid + 256 * i; int k = u / 28; int n4 = (u - k * 28) * 4;
                sv[i] = *(const float4*)&sb[(size_t)((t + 1) * KC + k) * Pn + n0 + n4];
            }
        }
        __syncthreads();
        uint32_t aHiB = sbase + buf * STG_E * 2;
        mma_chunk(acc, aHiB, aHiB + 2 * AEb, lane, warp_m, warp_n);
    }

    const int r0 = lane >> 2, c0 = (lane & 3) * 2;
#pragma unroll
    for (int i = 0; i < 2; i++) {
        const int mA = warp_m + i * 16 + r0;
        const int mB = mA + 8;
        const float scA = scale[mA], biA = bias[mA];
        const float scB = scale[mB], biB = bias[mB];
        float* dA = g_out1 + ((size_t)b * CMID + mA) * Pn;
        float* dB = g_out1 + ((size_t)b * CMID + mB) * Pn;
#pragma unroll
        for (int j = 0; j < 7; j++) {
            const int n = n0 + warp_n + j * 8 + c0;
            float2 vA = {fmaxf(acc[i][j][0] * scA + biA, 0.f),
                         fmaxf(acc[i][j][1] * scA + biA, 0.f)};
            float2 vB = {fmaxf(acc[i][j][2] * scB + biB, 0.f),
                         fmaxf(acc[i][j][3] * scB + biB, 0.f)};
            *(float2*)&dA[n] = vA;
            *(float2*)&dB[n] = vB;
        }
    }
}

// ============================================================================
// conv3: 128->512, BN + residual. Pre-split operands, pure cp.async, 2 CTAs/SM.
// ============================================================================
#define CONV3_SMEM (STG_E * 2)

__global__ __launch_bounds__(256, 2) void k_conv3mm(const float* __restrict__ scale,
                                                    const float* __restrict__ bias,
                                                    const float* __restrict__ x,
                                                    float* __restrict__ out) {
    extern __shared__ __align__(16) __nv_bfloat16 smb[];
    const int tid = threadIdx.x, wid = tid >> 5, lane = tid & 31;
    const int b = blockIdx.y, n0 = blockIdx.x * BN, mo = blockIdx.z * BM;
    const int warp_m = (wid >> 1) * 32, warp_n = (wid & 1) * 56;
    const uint32_t aHiB = smem_u32(smb);
    const uint32_t bHiB = aHiB + 2 * AEb;

    float acc[2][7][4];
#pragma unroll
    for (int i = 0; i < 2; i++)
#pragma unroll
        for (int j = 0; j < 7; j++)
#pragma unroll
            for (int q = 0; q < 4; q++) acc[i][j][q] = 0.f;

#pragma unroll 1
    for (int t = 0; t < 2; t++) {
        if (t) __syncthreads();
#pragma unroll
        for (int i = 0; i < 8; i++) {
            int q = tid + 256 * i;
            int plane = q >> 10, m = (q >> 3) & 127, j = q & 7;
            uint32_t dst = aHiB + (uint32_t)plane * AEb + (uint32_t)(m * SK + j * 8) * 2;
            const __nv_bfloat16* wp = plane ? g_w3l : g_w3h;
            cpa16(dst, wp + (size_t)(mo + m) * CMID + t * KC + j * 8);
        }
#pragma unroll
        for (int i = 0; i < 7; i++) {
            int q = tid + 256 * i;
            int plane = q >= 896;
            int r = plane ? q - 896 : q;
            int k = r / 14, j = r - k * 14;
            uint32_t dst = bHiB + (uint32_t)plane * BEb + (uint32_t)(k * SN + j * 8) * 2;
            const __nv_bfloat16* op = plane ? g_o2l : g_o2h;
            cpa16(dst, op + ((size_t)b * CMID + t * KC + k) * Pn + n0 + j * 8);
        }
        CP_COMMIT();
        CP_WAIT0();
        __syncthreads();
        mma_chunk(acc, aHiB, bHiB, lane, warp_m, warp_n);
    }

    const int r0 = lane >> 2, c0 = (lane & 3) * 2;
#pragma unroll
    for (int i = 0; i < 2; i++) {
        const int mA = mo + warp_m + i * 16 + r0;
        const int mB = mA + 8;
        const float scA = scale[mA], biA = bias[mA];
        const float scB = scale[mB], biB = bias[mB];
        float* dA = out + ((size_t)b * CIN + mA) * Pn;
        float* dB = out + ((size_t)b * CIN + mB) * Pn;
        const float* rA = x + ((size_t)b * CIN + mA) * Pn;
        const float* rB = x + ((size_t)b * CIN + mB) * Pn;
#pragma unroll
        for (int j = 0; j < 7; j++) {
            const int n = n0 + warp_n + j * 8 + c0;
            float2 qA = *(const float2*)&rA[n];
            float2 qB = *(const float2*)&rB[n];
            float2 vA = {acc[i][j][0] * scA + biA + qA.x,
                         acc[i][j][1] * scA + biA + qA.y};
            float2 vB = {acc[i][j][2] * scB + biB + qB.x,
                         acc[i][j][3] * scB + biB + qB.y};
            *(float2*)&dA[n] = vA;
            *(float2*)&dB[n] = vB;
        }
    }
}

// ---------------------------------------------------------------------------
// Pre-split: W3 -> g_w3h/l  and  Ws (padded to 400 rows) -> g_wsh/l
// ---------------------------------------------------------------------------
__global__ void k_splitw(const float* __restrict__ w3src,
                         const float* __restrict__ wssrc) {
    int i = blockIdx.x * 256 + threadIdx.x;
    if (i < CIN * CMID) {
        __nv_bfloat16 h, l;
        split2(w3src[i], h, l);
        g_w3h[i] = h;
        g_w3l[i] = l;
    }
    if (i < 400 * CRED) {
        float v = (i < CSPAN * CRED) ? wssrc[i] : 0.f;
        __nv_bfloat16 h, l;
        split2(v, h, l);
        g_wsh[i] = h;
        g_wsl[i] = l;
    }
}

// ---------------------------------------------------------------------------
// Kernel 2: involution kernel generation — SIMT reduce + tensor-core span.
// grid (7, 16), 256 threads, 101.4 KB smem -> 2 CTAs/SM.
//   1. t1 [128c][128n] fp32 + WrT to smem
//   2. reduce (4m x 4n / thread) -> BN+ReLU -> split-bf16 planes [32k][136n]
//   3. cp.async pre-split Ws A planes [400m][40k] into (dead) t1 region
//   4. span mma: warp = n16 strip; 25 m16 tiles x (8 ldsm + 12 HMMA + stores)
// ---------------------------------------------------------------------------
#define WRT_S 36
#define SK2 40
#define SN2 136
#define KG_A_LO   32000                       // aLo byte offset within A region
#define KG_WRT    65536                       // WrT byte offset
#define KG_BH     (KG_WRT + 128 * WRT_S * 4)  // 83968
#define KG_BPL    (32 * SN2 * 2)              // 8704 bytes per B plane
#define KGEN_SMEM (KG_BH + 2 * KG_BPL)        // 101376

__global__ __launch_bounds__(256) void k_kgen(const float* __restrict__ Wr,
                                              const float* __restrict__ sr,
                                              const float* __restrict__ br,
                                              const float* __restrict__ bs) {
    extern __shared__ __align__(16) char smc[];
    float* t1  = (float*)smc;
    float* WrT = (float*)(smc + KG_WRT);
    const uint32_t sbase = smem_u32(smc);

    const int b = blockIdx.y, n0 = blockIdx.x * 128, tid = threadIdx.x;
    const int wid = tid >> 5, lane = tid & 31;
    const float* o1 = g_out1 + (size_t)b * CMID * Pn;

    // t1 [128c][128n], zero-padded past Pn
#pragma unroll
    for (int i = 0; i < 16; i++) {
        int j = tid + 256 * i;
        int c = j >> 5, n4 = (j & 31) * 4;
        int n = n0 + n4;
        *(float4*)&t1[c * 128 + n4] =
            (n < Pn) ? *(const float4*)&o1[(size_t)c * Pn + n] : make_float4(0.f,0.f,0.f,0.f);
    }
#pragma unroll
    for (int i = 0; i < 16; i++) {
        int j = tid + 256 * i;
        int m = j >> 7, c = j & 127;
        WrT[c * WRT_S + m] = Wr[j];
    }
    __syncthreads();

    // ---- reduce: 4m x 4n per thread -> split-bf16 B planes ----
    {
        const int mt = tid >> 5;
        const int nn = (tid & 31) * 4;
        float racc[4][4];
#pragma unroll
        for (int i = 0; i < 4; i++)
#pragma unroll
            for (int j = 0; j < 4; j++) racc[i][j] = 0.f;
#pragma unroll 8
        for (int c = 0; c < 128; c++) {
            float4 av = *(const float4*)&WrT[c * WRT_S + mt * 4];
            float4 bv = *(const float4*)&t1[c * 128 + nn];
            float ar[4] = {av.x, av.y, av.z, av.w};
            float bc[4] = {bv.x, bv.y, bv.z, bv.w};
#pragma unroll
            for (int i = 0; i < 4; i++)
#pragma unroll
                for (int j = 0; j < 4; j++) racc[i][j] += ar[i] * bc[j];
        }
#pragma unroll
        for (int i = 0; i < 4; i++) {
            int m = mt * 4 + i;                       // k-row of span
            float s = sr[m], bb = br[m];
            float v0 = fmaxf(racc[i][0]*s+bb, 0.f);
            float v1 = fmaxf(racc[i][1]*s+bb, 0.f);
            float v2 = fmaxf(racc[i][2]*s+bb, 0.f);
            float v3 = fmaxf(racc[i][3]*s+bb, 0.f);
            __nv_bfloat16 h0,h1,h2,h3,l0,l1,l2,l3;
            split2(v0,h0,l0); split2(v1,h1,l1); split2(v2,h2,l2); split2(v3,h3,l3);
            char* dst = smc + KG_BH + (m * SN2 + nn) * 2;
            *(uint2*)dst            = make_uint2(pk2(h0,h1), pk2(h2,h3));
            *(uint2*)(dst + KG_BPL) = make_uint2(pk2(l0,l1), pk2(l2,l3));
        }
    }
    __syncthreads();

    // ---- cp.async Ws A planes [400m][SK2 k] into t1 region ----
#pragma unroll
    for (int i = 0; i < 13; i++) {
        int q = tid + 256 * i;
        if (q < 3200) {
            int pl = q >= 1600;
            int r = pl ? q - 1600 : q;
            int row = r >> 2, j = r & 3;
            uint32_t dst = sbase + (uint32_t)pl * KG_A_LO + (uint32_t)(row * SK2 + j * 8) * 2;
            const __nv_bfloat16* src = pl ? g_wsl : g_wsh;
            cpa16(dst, src + row * CRED + j * 8);
        }
    }
    CP_COMMIT();
    CP_WAIT0();
    __syncthreads();

    // ---- span mma: warp = n16 strip (nt = wid), loop 25 m16 tiles ----
    {
        const int r0 = lane >> 2, c0 = (lane & 3) * 2;
        const int l15 = lane & 15, l7 = lane & 7;
        const int nt = wid;
        const uint32_t bB = sbase + KG_BH;

        uint32_t rh[2][4], rl[2][4];
#pragma unroll
        for (int ks = 0; ks < 2; ks++) {
            uint32_t kr = (uint32_t)(ks * 16 + l7 + ((lane >> 3) & 1) * 8);
            uint32_t nc = (uint32_t)(nt * 16 + (lane >> 4) * 8);
            uint32_t bd = bB + (kr * SN2 + nc) * 2;
            ldsm_x4_t(rh[ks], bd);
            ldsm_x4_t(rl[ks], bd + KG_BPL);
        }

#pragma unroll 1
        for (int mt = 0; mt < 25; mt++) {
            const int mA = mt * 16 + r0, mB = mA + 8;
            const float bsA = (mA < CSPAN) ? __ldg(bs + mA) : 0.f;
            const float bsB = (mB < CSPAN) ? __ldg(bs + mB) : 0.f;
            float acc[2][4];
#pragma unroll
            for (int j = 0; j < 2; j++) {
                acc[j][0] = bsA; acc[j][1] = bsA;
                acc[j][2] = bsB; acc[j][3] = bsB;
            }
#pragma unroll
            for (int ks = 0; ks < 2; ks++) {
                uint32_t aRow = (uint32_t)((mt * 16 + l15) * SK2
                                + ((lane >> 4) & 1) * 8 + ks * 16);
                uint32_t ad = sbase + aRow * 2;
                uint32_t ah[4], al[4];
                ldsm_x4(ah, ad);
                ldsm_x4(al, ad + KG_A_LO);
#pragma unroll
                for (int j = 0; j < 2; j++) {
                    mma_bf16(acc[j], ah, rh[ks] + 2 * j);
                    mma_bf16(acc[j], ah, rl[ks] + 2 * j);
                    mma_bf16(acc[j], al, rh[ks] + 2 * j);
                }
            }
#pragma unroll
            for (int j = 0; j < 2; j++) {
                const int n = n0 + nt * 16 + j * 8 + c0;
                if (n < Pn) {
                    if (mA < CSPAN) {
                        float2 v = {acc[j][0], acc[j][1]};
                        *(float2*)&g_w[((size_t)b * CSPAN + mA) * Pn + n] = v;
                    }
                    if (mB < CSPAN) {
                        float2 v = {acc[j][2], acc[j][3]};
                        *(float2*)&g_w[((size_t)b * CSPAN + mB) * Pn + n] = v;
                    }
                }
            }
        }
    }
}

// ---------------------------------------------------------------------------
// Kernel 3: involution apply — R10 version (best known: 19.7us).
// Block = half-plane, 512 threads: thread = (pixel-pair, 8-channel half).
// ---------------------------------------------------------------------------
#define APL_SLOT 20
#define APL_SMEM (20 * 34 * APL_SLOT * 4)   // 54,400 B

__global__ __launch_bounds__(512, 2) void k_apply() {
    extern __shared__ __align__(16) float xs[];
    const int y0 = blockIdx.x * 14;
    const int g  = blockIdx.y;
    const int b  = blockIdx.z;
    const int tid = threadIdx.x;

    const float* o1 = g_out1 + (b * CMID + g * 16) * Pn;
    for (int j = tid; j < 20 * 34 * 16; j += 512) {
        int c    = j & 15;
        int slot = j >> 4;
        int xx = slot % 34, yy = slot / 34;
        int gy = y0 + yy - 3, gx = xx - 3;
        float v = 0.f;
        if (gy >= 0 && gy < 28 && gx >= 0 && gx < 28)
            v = o1[c * Pn + gy * 28 + gx];
        xs[slot * APL_SLOT + c] = v;
    }
    __syncthreads();

    if (tid < 392) {
        const int h = tid / 196;
        const int p = tid - h * 196;
        const int yA = (p / 28) * 2;
        const int xc = p % 28;
        const int hwA = (y0 + yA) * 28 + xc;
        const int hwB = hwA + 28;
        const float* wbase = g_w + ((size_t)b * CSPAN + (size_t)g * KK) * Pn;

        float accA[8], accB[8];
#pragma unroll
        for (int c = 0; c < 8; c++) { accA[c] = 0.f; accB[c] = 0.f; }

#pragma unroll
        for (int dx = 0; dx < 7; dx++) {
            float wA[7], wB[7];
#pragma unroll
            for (int dy = 0; dy < 7; dy++) {
                const size_t wo = (size_t)(dy * 7 + dx) * Pn;
                wA[dy] = wbase[wo + hwA];
                wB[dy] = wbase[wo + hwB];
            }
#pragma unroll
            for (int i = 0; i < 8; i++) {
                const float* base = &xs[((yA + i) * 34 + xc + dx) * APL_SLOT + h * 8];
                float4 v0 = *(const float4*)&base[0];
                float4 v1 = *(const float4*)&base[4];
                if (i < 7) {
                    const float w = wA[i];
                    accA[0] += w*v0.x; accA[1] += w*v0.y; accA[2] += w*v0.z; accA[3] += w*v0.w;
                    accA[4] += w*v1.x; accA[5] += w*v1.y; accA[6] += w*v1.z; accA[7] += w*v1.w;
                }
                if (i >= 1) {
                    const float w = wB[i - 1];
                    accB[0] += w*v0.x; accB[1] += w*v0.y; accB[2] += w*v0.z; accB[3] += w*v0.w;
                    accB[4] += w*v1.x; accB[5] += w*v1.y; accB[6] += w*v1.z; accB[7] += w*v1.w;
                }
            }
        }

        const size_t baseA = (size_t)(b * CMID + g * 16 + h * 8) * Pn + hwA;
#pragma unroll
        for (int c = 0; c < 8; c++) {
            __nv_bfloat16 hh, ll;
            split2(accA[c], hh, ll);
            g_o2h[baseA + (size_t)c * Pn] = hh;
            g_o2l[baseA + (size_t)c * Pn] = ll;
        }
#pragma unroll
        for (int c = 0; c < 8; c++) {
            __nv_bfloat16 hh, ll;
            split2(accB[c], hh, ll);
            g_o2h[baseA + 28 + (size_t)c * Pn] = hh;
            g_o2l[baseA + 28 + (size_t)c * Pn] = ll;
        }
    }
}

// ---------------------------------------------------------------------------
extern "C" void kernel_launch(void* const* d_in, const int* in_sizes, int n_in,
                              void* d_out, int out_size) {
    const float* x  = (const float*)d_in[0];
    const float* W1 = (const float*)d_in[1];
    const float* s1 = (const float*)d_in[2];
    const float* b1 = (const float*)d_in[3];
    const float* Wr = (const float*)d_in[4];
    const float* sr = (const float*)d_in[5];
    const float* br = (const float*)d_in[6];
    const float* Ws = (const float*)d_in[7];
    const float* bs = (const float*)d_in[8];
    const float* W3 = (const float*)d_in[9];
    const float* s3 = (const float*)d_in[10];
    const float* b3 = (const float*)d_in[11];
    float* out = (float*)d_out;

    cudaFuncSetAttribute(k_kgen, cudaFuncAttributeMaxDynamicSharedMemorySize, KGEN_SMEM);
    cudaFuncSetAttribute(k_apply, cudaFuncAttributeMaxDynamicSharedMemorySize, APL_SMEM);
    cudaFuncSetAttribute(k_conv1mm, cudaFuncAttributeMaxDynamicSharedMemorySize, CONV1_SMEM);
    cudaFuncSetAttribute(k_conv3mm, cudaFuncAttributeMaxDynamicSharedMemorySize, CONV3_SMEM);

    // pre-split W3 and Ws (independent of everything else)
    k_splitw<<<(CIN * CMID + 255) / 256, 256>>>(W3, Ws);
    // conv1: 512 -> 128, BN+ReLU
    k_conv1mm<<<dim3(7, 16), 256, CONV1_SMEM>>>(W1, s1, b1, x);
    // involution kernel generation (tensor-core span)
    k_kgen<<<dim3(7, 16), 256, KGEN_SMEM>>>(Wr, sr, br, bs);
    // involution apply (R10 best config, emits split-bf16 o2)
    k_apply<<<dim3(2, NG, BATCH), 512, APL_SMEM>>>();
    // conv3: 128 -> 512, BN + residual
    k_conv3mm<<<dim3(7, 16, 4), 256, CONV3_SMEM>>>(s3, b3, x, out);
}